// round 5
// baseline (speedup 1.0000x reference)
#include <cuda_runtime.h>

#define IN_DIM 256
#define FEAT   33152      // 256 + (256 + 256*256)/2 = 259 * 128
#define NB     8          // batch
#define NROWS  8192       // NHEAD * S * D_MODEL
#define KITERS (FEAT / 128)   // 259, exact
#define OUTF   64

typedef unsigned long long u64;

// scratch (allocation-free rule: __device__ globals)
__device__ __align__(16) float g_feats[NB * FEAT];
__device__ __align__(16) float g_head[NB * NROWS];

// packed dual-FMA: d.lo = a.lo*b.lo + c.lo ; d.hi = a.hi*b.hi + c.hi
__device__ __forceinline__ u64 ffma2(u64 a, u64 b, u64 c) {
    u64 d;
    asm("fma.rn.f32x2 %0, %1, %2, %3;" : "=l"(d) : "l"(a), "l"(b), "l"(c));
    return d;
}

__device__ __forceinline__ float sum2(u64 v) {
    union { u64 u; float f[2]; } cvt;
    cvt.u = v;
    return cvt.f[0] + cvt.f[1];
}

// streaming (evict-first) 16B load for the 1-GB W stream
__device__ __forceinline__ ulonglong2 ldcs128(const void* p) {
    ulonglong2 v;
    asm volatile("ld.global.cs.v2.u64 {%0, %1}, [%2];"
                 : "=l"(v.x), "=l"(v.y) : "l"(p));
    return v;
}

// default-cached (L1-resident) 16B load for feats
__device__ __forceinline__ ulonglong2 ldca128(const void* p) {
    ulonglong2 v;
    asm("ld.global.ca.v2.u64 {%0, %1}, [%2];"
        : "=l"(v.x), "=l"(v.y) : "l"(p));
    return v;
}

// ---------------------------------------------------------------------------
// Kernel A: build feats = [x_flat | triu(x x^T)] for all 8 batches.
// ---------------------------------------------------------------------------
__global__ void build_feats_kernel(const float* __restrict__ x) {
    __shared__ float xs[NB][IN_DIM];
    int tid = threadIdx.x;                       // 256 threads
    for (int t = tid; t < NB * IN_DIM; t += 256)
        xs[t >> 8][t & 255] = x[t];
    __syncthreads();

    int i = blockIdx.x;
    if (i < IN_DIM) {
        int j = tid;
        if (j >= i) {
            int off = IN_DIM + i * IN_DIM - (i * (i - 1)) / 2 + (j - i);
            #pragma unroll
            for (int b = 0; b < NB; b++)
                g_feats[b * FEAT + off] = xs[b][i] * xs[b][j];
        }
    } else {
        int j = tid;
        #pragma unroll
        for (int b = 0; b < NB; b++)
            g_feats[b * FEAT + j] = xs[b][j];
    }
}

// ---------------------------------------------------------------------------
// Kernel B: head_out[b][r] = dot(feats[b], W[r]) + bh[r]
//   Sync-free, smem-free. W register-double-buffered: iteration it prefetches
//   it+1's W slice before consuming it's, doubling in-flight DRAM loads.
//   feats served from L1 (.ca). 1024 blocks x 64 thr, 4 rows/warp.
// ---------------------------------------------------------------------------
__global__ void __launch_bounds__(64, 7)
head_gemm_kernel(const float* __restrict__ W, const float* __restrict__ bh) {
    int warp = threadIdx.x >> 5;                 // 0..1
    int lane = threadIdx.x & 31;
    int row0 = blockIdx.x * 8 + warp * 4;

    const float* w0 = W + (size_t)row0 * FEAT + lane * 4;
    const float* w1 = w0 + FEAT;
    const float* w2 = w1 + FEAT;
    const float* w3 = w2 + FEAT;
    const float* fb = g_feats + lane * 4;

    u64 acc[4][8];
    #pragma unroll
    for (int r = 0; r < 4; r++)
        #pragma unroll
        for (int b = 0; b < 8; b++) acc[r][b] = 0ull;

    // prologue: load k-slice 0
    ulonglong2 a0 = ldcs128(w0);
    ulonglong2 a1 = ldcs128(w1);
    ulonglong2 a2 = ldcs128(w2);
    ulonglong2 a3 = ldcs128(w3);

    #pragma unroll 2
    for (int it = 0; it < KITERS - 1; it++) {
        int k  = it * 128;
        int kn = k + 128;
        // prefetch next W slice (independent of everything below)
        ulonglong2 n0 = ldcs128(w0 + kn);
        ulonglong2 n1 = ldcs128(w1 + kn);
        ulonglong2 n2 = ldcs128(w2 + kn);
        ulonglong2 n3 = ldcs128(w3 + kn);
        #pragma unroll
        for (int b = 0; b < 8; b++) {
            ulonglong2 f = ldca128(fb + b * FEAT + k);
            acc[0][b] = ffma2(a0.x, f.x, acc[0][b]);
            acc[0][b] = ffma2(a0.y, f.y, acc[0][b]);
            acc[1][b] = ffma2(a1.x, f.x, acc[1][b]);
            acc[1][b] = ffma2(a1.y, f.y, acc[1][b]);
            acc[2][b] = ffma2(a2.x, f.x, acc[2][b]);
            acc[2][b] = ffma2(a2.y, f.y, acc[2][b]);
            acc[3][b] = ffma2(a3.x, f.x, acc[3][b]);
            acc[3][b] = ffma2(a3.y, f.y, acc[3][b]);
        }
        a0 = n0; a1 = n1; a2 = n2; a3 = n3;
    }

    // epilogue: last k-slice
    {
        int k = (KITERS - 1) * 128;
        #pragma unroll
        for (int b = 0; b < 8; b++) {
            ulonglong2 f = ldca128(fb + b * FEAT + k);
            acc[0][b] = ffma2(a0.x, f.x, acc[0][b]);
            acc[0][b] = ffma2(a0.y, f.y, acc[0][b]);
            acc[1][b] = ffma2(a1.x, f.x, acc[1][b]);
            acc[1][b] = ffma2(a1.y, f.y, acc[1][b]);
            acc[2][b] = ffma2(a2.x, f.x, acc[2][b]);
            acc[2][b] = ffma2(a2.y, f.y, acc[2][b]);
            acc[3][b] = ffma2(a3.x, f.x, acc[3][b]);
            acc[3][b] = ffma2(a3.y, f.y, acc[3][b]);
        }
    }

    // per-(row,batch): fold k-parity halves, warp-reduce, write
    #pragma unroll
    for (int r = 0; r < 4; r++) {
        #pragma unroll
        for (int b = 0; b < 8; b++) {
            float v = sum2(acc[r][b]);
            #pragma unroll
            for (int o = 16; o > 0; o >>= 1)
                v += __shfl_xor_sync(0xffffffffu, v, o);
            if (lane == 0)
                g_head[b * NROWS + row0 + r] = v + bh[row0 + r];
        }
    }
}

// ---------------------------------------------------------------------------
// Kernel C: out[b][s][o] = dot(concat[b][s], W_out[o]) + b_out[o]
// ---------------------------------------------------------------------------
__global__ void out_gemm_kernel(const float* __restrict__ Wout,
                                const float* __restrict__ bout,
                                float* __restrict__ out) {
    __shared__ float cs[256];
    int bs = blockIdx.x;
    int b  = bs >> 5;
    int s  = bs & 31;
    int t  = threadIdx.x;    // 64 threads

    #pragma unroll
    for (int q = 0; q < 4; q++) {
        int j = t + q * 64;
        cs[j] = g_head[b * NROWS + (j >> 6) * 2048 + s * 64 + (j & 63)];
    }
    __syncthreads();

    const float* wr = Wout + t * 256;
    float sum = bout[t];
    #pragma unroll
    for (int j = 0; j < 256; j += 4) {
        float4 w = *(const float4*)(wr + j);
        sum = fmaf(w.x, cs[j],
              fmaf(w.y, cs[j + 1],
              fmaf(w.z, cs[j + 2],
              fmaf(w.w, cs[j + 3], sum))));
    }
    out[bs * 64 + t] = sum;
}

// ---------------------------------------------------------------------------
extern "C" void kernel_launch(void* const* d_in, const int* in_sizes, int n_in,
                              void* d_out, int out_size) {
    const float* x   = (const float*)d_in[0];   // (8,32,8)
    const float* W   = (const float*)d_in[1];   // (4,2048,33152)
    const float* bh  = (const float*)d_in[2];   // (4,2048)
    const float* Wo  = (const float*)d_in[3];   // (64,256)
    const float* bo  = (const float*)d_in[4];   // (64,)
    float* out = (float*)d_out;                 // (8,32,64)

    build_feats_kernel<<<IN_DIM + 1, 256>>>(x);
    head_gemm_kernel<<<NROWS / 8, 64>>>(W, bh);
    out_gemm_kernel<<<256, 64>>>(Wo, bo, out);
}

// round 6
// speedup vs baseline: 1.3757x; 1.3757x over previous
#include <cuda_runtime.h>

#define IN_DIM 256
#define FEAT   33152      // 256 + (256 + 256*256)/2 = 259 * 128
#define NB     8          // batch
#define NROWS  8192       // NHEAD * S * D_MODEL
#define KITERS (FEAT / 128)   // 259, exact
#define OUTF   64

typedef unsigned long long u64;

// scratch (allocation-free rule: __device__ globals)
__device__ __align__(16) float g_feats[NB * FEAT];
__device__ __align__(16) float g_head[NB * NROWS];

// packed dual-FMA: d.lo = a.lo*b.lo + c.lo ; d.hi = a.hi*b.hi + c.hi
__device__ __forceinline__ u64 ffma2(u64 a, u64 b, u64 c) {
    u64 d;
    asm("fma.rn.f32x2 %0, %1, %2, %3;" : "=l"(d) : "l"(a), "l"(b), "l"(c));
    return d;
}

__device__ __forceinline__ float sum2(u64 v) {
    union { u64 u; float f[2]; } cvt;
    cvt.u = v;
    return cvt.f[0] + cvt.f[1];
}

// streaming (evict-first) 16B load for the 1-GB W stream
__device__ __forceinline__ ulonglong2 ldcs128(const void* p) {
    ulonglong2 v;
    asm volatile("ld.global.cs.v2.u64 {%0, %1}, [%2];"
                 : "=l"(v.x), "=l"(v.y) : "l"(p));
    return v;
}

// default-cached (L1-resident) 16B load for feats
__device__ __forceinline__ ulonglong2 ldca128(const void* p) {
    ulonglong2 v;
    asm("ld.global.ca.v2.u64 {%0, %1}, [%2];"
        : "=l"(v.x), "=l"(v.y) : "l"(p));
    return v;
}

// ---------------------------------------------------------------------------
// Kernel A: build feats = [x_flat | triu(x x^T)] for all 8 batches.
// ---------------------------------------------------------------------------
__global__ void build_feats_kernel(const float* __restrict__ x) {
    __shared__ float xs[NB][IN_DIM];
    int tid = threadIdx.x;                       // 256 threads
    for (int t = tid; t < NB * IN_DIM; t += 256)
        xs[t >> 8][t & 255] = x[t];
    __syncthreads();

    int i = blockIdx.x;
    if (i < IN_DIM) {
        int j = tid;
        if (j >= i) {
            int off = IN_DIM + i * IN_DIM - (i * (i - 1)) / 2 + (j - i);
            #pragma unroll
            for (int b = 0; b < NB; b++)
                g_feats[b * FEAT + off] = xs[b][i] * xs[b][j];
        }
    } else {
        int j = tid;
        #pragma unroll
        for (int b = 0; b < NB; b++)
            g_feats[b * FEAT + j] = xs[b][j];
    }
}

// ---------------------------------------------------------------------------
// Kernel B: head_out[b][r] = dot(feats[b], W[r]) + bh[r]
//   1 warp per block, 8 rows per warp, all 8 batches -> 64 dot-updates per
//   16 LDG.128 (0.25 loads/update vs 0.375 before). Sync-free, smem-free;
//   feats via L1 (.ca), W streamed (.cs). grid=1024, ~7 blocks/SM.
// ---------------------------------------------------------------------------
__global__ void __launch_bounds__(32, 8)
head_gemm_kernel(const float* __restrict__ W, const float* __restrict__ bh) {
    int lane = threadIdx.x & 31;
    int row0 = blockIdx.x * 8;

    const float* wbase = W + (size_t)row0 * FEAT + lane * 4;
    const float* fb    = g_feats + lane * 4;

    u64 acc[8][8];
    #pragma unroll
    for (int r = 0; r < 8; r++)
        #pragma unroll
        for (int b = 0; b < 8; b++) acc[r][b] = 0ull;

    #pragma unroll 1
    for (int it = 0; it < KITERS; it++) {
        int k = it * 128;
        const float* wk = wbase + k;
        ulonglong2 a0 = ldcs128(wk);
        ulonglong2 a1 = ldcs128(wk + 1 * FEAT);
        ulonglong2 a2 = ldcs128(wk + 2 * FEAT);
        ulonglong2 a3 = ldcs128(wk + 3 * FEAT);
        ulonglong2 a4 = ldcs128(wk + 4 * FEAT);
        ulonglong2 a5 = ldcs128(wk + 5 * FEAT);
        ulonglong2 a6 = ldcs128(wk + 6 * FEAT);
        ulonglong2 a7 = ldcs128(wk + 7 * FEAT);
        const float* fk = fb + k;
        #pragma unroll
        for (int b = 0; b < 8; b++) {
            ulonglong2 f = ldca128(fk + b * FEAT);
            acc[0][b] = ffma2(a0.x, f.x, acc[0][b]);
            acc[0][b] = ffma2(a0.y, f.y, acc[0][b]);
            acc[1][b] = ffma2(a1.x, f.x, acc[1][b]);
            acc[1][b] = ffma2(a1.y, f.y, acc[1][b]);
            acc[2][b] = ffma2(a2.x, f.x, acc[2][b]);
            acc[2][b] = ffma2(a2.y, f.y, acc[2][b]);
            acc[3][b] = ffma2(a3.x, f.x, acc[3][b]);
            acc[3][b] = ffma2(a3.y, f.y, acc[3][b]);
            acc[4][b] = ffma2(a4.x, f.x, acc[4][b]);
            acc[4][b] = ffma2(a4.y, f.y, acc[4][b]);
            acc[5][b] = ffma2(a5.x, f.x, acc[5][b]);
            acc[5][b] = ffma2(a5.y, f.y, acc[5][b]);
            acc[6][b] = ffma2(a6.x, f.x, acc[6][b]);
            acc[6][b] = ffma2(a6.y, f.y, acc[6][b]);
            acc[7][b] = ffma2(a7.x, f.x, acc[7][b]);
            acc[7][b] = ffma2(a7.y, f.y, acc[7][b]);
        }
    }

    // per-(row,batch): fold k-parity halves, warp-reduce, write
    #pragma unroll
    for (int r = 0; r < 8; r++) {
        #pragma unroll
        for (int b = 0; b < 8; b++) {
            float v = sum2(acc[r][b]);
            #pragma unroll
            for (int o = 16; o > 0; o >>= 1)
                v += __shfl_xor_sync(0xffffffffu, v, o);
            if (lane == 0)
                g_head[b * NROWS + row0 + r] = v + bh[row0 + r];
        }
    }
}

// ---------------------------------------------------------------------------
// Kernel C: out[b][s][o] = dot(concat[b][s], W_out[o]) + b_out[o]
// ---------------------------------------------------------------------------
__global__ void out_gemm_kernel(const float* __restrict__ Wout,
                                const float* __restrict__ bout,
                                float* __restrict__ out) {
    __shared__ float cs[256];
    int bs = blockIdx.x;
    int b  = bs >> 5;
    int s  = bs & 31;
    int t  = threadIdx.x;    // 64 threads

    #pragma unroll
    for (int q = 0; q < 4; q++) {
        int j = t + q * 64;
        cs[j] = g_head[b * NROWS + (j >> 6) * 2048 + s * 64 + (j & 63)];
    }
    __syncthreads();

    const float* wr = Wout + t * 256;
    float sum = bout[t];
    #pragma unroll
    for (int j = 0; j < 256; j += 4) {
        float4 w = *(const float4*)(wr + j);
        sum = fmaf(w.x, cs[j],
              fmaf(w.y, cs[j + 1],
              fmaf(w.z, cs[j + 2],
              fmaf(w.w, cs[j + 3], sum))));
    }
    out[bs * 64 + t] = sum;
}

// ---------------------------------------------------------------------------
extern "C" void kernel_launch(void* const* d_in, const int* in_sizes, int n_in,
                              void* d_out, int out_size) {
    const float* x   = (const float*)d_in[0];   // (8,32,8)
    const float* W   = (const float*)d_in[1];   // (4,2048,33152)
    const float* bh  = (const float*)d_in[2];   // (4,2048)
    const float* Wo  = (const float*)d_in[3];   // (64,256)
    const float* bo  = (const float*)d_in[4];   // (64,)
    float* out = (float*)d_out;                 // (8,32,64)

    build_feats_kernel<<<IN_DIM + 1, 256>>>(x);
    head_gemm_kernel<<<NROWS / 8, 32>>>(W, bh);
    out_gemm_kernel<<<256, 64>>>(Wo, bo, out);
}